// round 2
// baseline (speedup 1.0000x reference)
#include <cuda_runtime.h>

// Model_PDE_2: N=131072 points, H=1024 hidden tanh units, D=2.
//   t   = tanh(x0*a_h + x1*b_h + c_h)
//   out = sum_h t*w_h + b2
//   g0  = C0 - sum_h t^2 * (w*a)_h        (df_dt)   C0 = sum wa
//   g1  = C1 - sum_h t^2 * (w*b)_h        (df_dx)   C1 = sum wb
//   dxdx= sum_h (t - t^3) * (-2*w*b^2)_h  (df_dxdx)
//   pde = 0.5*x1^2 + g0 + 0.5*dxdx + 0.5*x1*g1 - (0.25/3.6)*g1^2
// Output layout: d_out[0..N) = out, d_out[N..2N) = pde.

#define HID 1024
#define TPB 256
#define PTS 2  // points per thread

// Scratch (no device allocations allowed): derived per-h weights, 8 floats/h:
// {a, b, c, w, wa, wb, wbb, 0}
__device__ float g_w8[HID * 8];
__device__ float g_c01[2];

__global__ void setup_kernel(const float* __restrict__ W1,
                             const float* __restrict__ b1,
                             const float* __restrict__ w2) {
    __shared__ float redA[HID];
    __shared__ float redB[HID];
    int h = threadIdx.x;
    float a = W1[2 * h], b = W1[2 * h + 1];
    float c = b1[h], w = w2[h];
    float wa = w * a;
    float wb = w * b;
    float wbb = -2.0f * w * b * b;
    float4* p = reinterpret_cast<float4*>(&g_w8[8 * h]);
    p[0] = make_float4(a, b, c, w);
    p[1] = make_float4(wa, wb, wbb, 0.0f);
    redA[h] = wa;
    redB[h] = wb;
    __syncthreads();
    for (int s = HID / 2; s > 0; s >>= 1) {
        if (h < s) {
            redA[h] += redA[h + s];
            redB[h] += redB[h + s];
        }
        __syncthreads();
    }
    if (h == 0) {
        g_c01[0] = redA[0];
        g_c01[1] = redB[0];
    }
}

__device__ __forceinline__ float tanh_fast(float z) {
    float t;
    asm("tanh.approx.f32 %0, %1;" : "=f"(t) : "f"(z));
    return t;
}

__global__ __launch_bounds__(TPB) void pde_kernel(const float* __restrict__ x,
                                                  const float* __restrict__ b2,
                                                  float* __restrict__ out,
                                                  int N) {
    __shared__ float4 sw[HID * 2];  // 32 KB: {a,b,c,w} and {wa,wb,wbb,0} per h

    const float4* gp = reinterpret_cast<const float4*>(g_w8);
    for (int i = threadIdx.x; i < HID * 2; i += TPB) sw[i] = gp[i];
    __syncthreads();

    // Block handles TPB*PTS consecutive points; thread handles PTS points
    // strided by TPB (keeps both the float2 loads and the stores coalesced).
    int base = blockIdx.x * (TPB * PTS) + threadIdx.x;

    float x0[PTS], x1[PTS];
    float acc_out[PTS], acc_gA[PTS], acc_gB[PTS], acc_dx[PTS];
#pragma unroll
    for (int i = 0; i < PTS; i++) {
        int n = base + i * TPB;
        float2 xv = (n < N) ? reinterpret_cast<const float2*>(x)[n]
                            : make_float2(0.0f, 0.0f);
        x0[i] = xv.x;
        x1[i] = xv.y;
        acc_out[i] = 0.0f;
        acc_gA[i] = 0.0f;
        acc_gB[i] = 0.0f;
        acc_dx[i] = 0.0f;
    }

#pragma unroll 4
    for (int h = 0; h < HID; h++) {
        float4 w0 = sw[2 * h];
        float4 w1 = sw[2 * h + 1];
#pragma unroll
        for (int i = 0; i < PTS; i++) {
            float z = __fmaf_rn(x1[i], w0.y, __fmaf_rn(x0[i], w0.x, w0.z));
            float t = tanh_fast(z);
            float tt = t * t;
            acc_out[i] = __fmaf_rn(t, w0.w, acc_out[i]);
            acc_gA[i] = __fmaf_rn(tt, w1.x, acc_gA[i]);
            acc_gB[i] = __fmaf_rn(tt, w1.y, acc_gB[i]);
            float p = __fmaf_rn(-t, tt, t);  // t - t^3
            acc_dx[i] = __fmaf_rn(p, w1.z, acc_dx[i]);
        }
    }

    float C0 = g_c01[0];
    float C1 = g_c01[1];
    float bias2 = b2[0];

#pragma unroll
    for (int i = 0; i < PTS; i++) {
        int n = base + i * TPB;
        if (n >= N) continue;
        float g0 = C0 - acc_gA[i];  // df_dt
        float g1 = C1 - acc_gB[i];  // df_dx
        float outv = acc_out[i] + bias2;

        // pde = 0.5*x1^2 + g0 + 0.5*dxdx + 0.5*x1*g1 - (0.25/(4*0.9))*g1^2
        float pde = __fmaf_rn(0.5f * x1[i], x1[i], g0);
        pde = __fmaf_rn(0.5f, acc_dx[i], pde);
        pde = __fmaf_rn(0.5f * x1[i], g1, pde);
        pde = __fmaf_rn(-0.069444444444444444f * g1, g1, pde);

        out[n] = outv;
        out[N + n] = pde;
    }
}

extern "C" void kernel_launch(void* const* d_in, const int* in_sizes, int n_in,
                              void* d_out, int out_size) {
    const float* x = (const float*)d_in[0];
    const float* W1 = (const float*)d_in[1];
    const float* b1 = (const float*)d_in[2];
    const float* w2 = (const float*)d_in[3];
    const float* b2 = (const float*)d_in[4];
    int N = in_sizes[0] / 2;

    setup_kernel<<<1, HID>>>(W1, b1, w2);
    int pts_per_block = TPB * PTS;
    pde_kernel<<<(N + pts_per_block - 1) / pts_per_block, TPB>>>(x, b2,
                                                                 (float*)d_out, N);
}